// round 8
// baseline (speedup 1.0000x reference)
#include <cuda_runtime.h>

// GenLoss, fully fused single kernel.
// combined = mean_b( masked-mean_c( MAE(out,target)[b,c] ) ) - 0.01*mean(labels)/(epoch+1)
//
// 768 image blocks + 8 label blocks (776 total, single wave: launch_bounds
// guarantees 8 blocks/SM -> 1184 slots >= 776). Each block writes its partial,
// fences, then sets a DISTINCT per-block flag (no contended atomics — that was
// R4's 11us tail). The last label block doubles as finalizer: it spins on the
// 775 flags, folds all partials in fixed order (deterministic), writes the
// scalar, and resets the flags for the next graph replay.

#define PLANES      48
#define BPP         16
#define RBLOCKS     (PLANES * BPP)     // 768
#define LBLOCKS     8
#define TOTAL_BLK   (RBLOCKS + LBLOCKS) // 776
#define FIN_BLK     (TOTAL_BLK - 1)
#define THREADS     256
#define PLANE_ELEMS (512*512)
#define BLOCK_ELEMS (PLANE_ELEMS/BPP)          // 16384
#define VEC_ITERS   (BLOCK_ELEMS/(THREADS*4))  // 16

__device__ float g_psum[RBLOCKS];
__device__ int   g_pflag[RBLOCKS];
__device__ float g_lsum[LBLOCKS];
__device__ int   g_flag[TOTAL_BLK];   // zero-init; reset by finalizer each run

__global__ void __launch_bounds__(THREADS, 8)
k_genloss(const float* __restrict__ out_img, const float* __restrict__ tgt_img,
          const float* __restrict__ labels, int n_labels,
          const int* __restrict__ epoch, float* __restrict__ out)
{
    const int tid = threadIdx.x;
    const int wid = tid >> 5;
    const int lid = tid & 31;
    const int bid = blockIdx.x;

    __shared__ float ss[THREADS / 32];
    __shared__ int   sf[THREADS / 32];

    if (bid < RBLOCKS) {
        // ---- image MAE partial over 1/16th of one plane ----
        const int plane = bid / BPP;
        const int sub   = bid % BPP;
        const long base = (long)plane * PLANE_ELEMS + (long)sub * BLOCK_ELEMS;

        const float4* __restrict__ o = (const float4*)(out_img + base);
        const float4* __restrict__ t = (const float4*)(tgt_img + base);

        float s = 0.0f;
        int   flag = 0;
        #pragma unroll
        for (int j = 0; j < VEC_ITERS; j++) {
            float4 a = o[tid + j * THREADS];
            float4 b = t[tid + j * THREADS];
            s += fabsf(a.x - b.x) + fabsf(a.y - b.y)
               + fabsf(a.z - b.z) + fabsf(a.w - b.w);
            flag |= (b.x != 0.0f) | (b.y != 0.0f) | (b.z != 0.0f) | (b.w != 0.0f);
        }
        #pragma unroll
        for (int off = 16; off; off >>= 1) {
            s    += __shfl_down_sync(0xffffffffu, s, off);
            flag |= __shfl_down_sync(0xffffffffu, flag, off);
        }
        if (lid == 0) { ss[wid] = s; sf[wid] = flag; }
        __syncthreads();
        if (tid == 0) {
            float bs = 0.0f; int bf = 0;
            #pragma unroll
            for (int w = 0; w < THREADS / 32; w++) { bs += ss[w]; bf |= sf[w]; }
            g_psum[bid]  = bs;
            g_pflag[bid] = bf;
            __threadfence();
            g_flag[bid] = 1;          // distinct address: plain store, no contention
        }
        return;
    }

    // ---- label partial sum (blocks 768..775) ----
    const int lb = bid - RBLOCKS;
    {
        float s = 0.0f;
        for (int i = lb * THREADS + tid; i < n_labels; i += LBLOCKS * THREADS)
            s += labels[i];
        #pragma unroll
        for (int off = 16; off; off >>= 1)
            s += __shfl_down_sync(0xffffffffu, s, off);
        if (lid == 0) ss[wid] = s;
        __syncthreads();
        if (tid == 0) {
            float bs = 0.0f;
            #pragma unroll
            for (int w = 0; w < THREADS / 32; w++) bs += ss[w];
            g_lsum[lb] = bs;
            if (bid != FIN_BLK) {
                __threadfence();
                g_flag[bid] = 1;
            }
        }
    }
    if (bid != FIN_BLK) return;

    // ================= finalizer (block 775) =================
    // Spin until all other 775 blocks have flagged. Grid is one wave
    // (8 blocks/SM * 148 SMs = 1184 >= 776), so no deadlock.
    {
        volatile int* vf = g_flag;
        for (int i = tid; i < TOTAL_BLK - 1; i += THREADS) {
            while (vf[i] == 0) __nanosleep(64);
        }
    }
    __syncthreads();
    __threadfence();   // acquire: order partial reads after flag observation

    __shared__ float sp[RBLOCKS];
    __shared__ int   sfl[RBLOCKS];
    __shared__ float plane_mae[PLANES];
    __shared__ int   plane_valid[PLANES];

    // Parallel vectorized fetch of partials (one latency round-trip).
    const float4* ps4 = (const float4*)g_psum;
    const int4*   pf4 = (const int4*)g_pflag;
    if (tid < RBLOCKS / 4) {
        float4 v = ps4[tid];
        int4   f = pf4[tid];
        sp[tid * 4 + 0] = v.x;  sp[tid * 4 + 1] = v.y;
        sp[tid * 4 + 2] = v.z;  sp[tid * 4 + 3] = v.w;
        sfl[tid * 4 + 0] = f.x; sfl[tid * 4 + 1] = f.y;
        sfl[tid * 4 + 2] = f.z; sfl[tid * 4 + 3] = f.w;
    }
    __syncthreads();

    if (tid < PLANES) {
        float s = 0.0f; int f = 0;
        #pragma unroll
        for (int i = 0; i < BPP; i++) {
            s += sp[tid * BPP + i];
            f |= sfl[tid * BPP + i];
        }
        plane_mae[tid]   = s * (1.0f / (float)PLANE_ELEMS);
        plane_valid[tid] = f;
    }
    __syncthreads();

    if (tid == 0) {
        float lsum = 0.0f;
        #pragma unroll
        for (int i = 0; i < LBLOCKS; i++) lsum += g_lsum[i];
        const float lmean = lsum / (float)n_labels;

        float img = 0.0f;
        #pragma unroll
        for (int b = 0; b < 16; b++) {
            float tot = 0.0f, cnt = 0.0f;
            #pragma unroll
            for (int c = 0; c < 3; c++) {
                const int p = b * 3 + c;
                if (plane_valid[p]) { tot += plane_mae[p]; cnt += 1.0f; }
            }
            img += (cnt > 0.0f) ? (tot / cnt) : 0.0f;
        }
        img *= (1.0f / 16.0f);

        out[0] = img + 0.01f * (-lmean) / (float)(epoch[0] + 1);
    }

    // Reset flags for the next graph replay (kernel-exit ordering makes this
    // safe: the next launch cannot begin until this kernel retires).
    __syncthreads();
    for (int i = tid; i < TOTAL_BLK; i += THREADS) g_flag[i] = 0;
}

extern "C" void kernel_launch(void* const* d_in, const int* in_sizes, int n_in,
                              void* d_out, int out_size)
{
    const float* labels  = (const float*)d_in[0];
    const float* out_img = (const float*)d_in[1];
    const float* tgt_img = (const float*)d_in[2];
    const int*   epoch   = (const int*)d_in[3];
    float*       out     = (float*)d_out;

    k_genloss<<<TOTAL_BLK, THREADS>>>(out_img, tgt_img, labels, in_sizes[0], epoch, out);
}

// round 9
// speedup vs baseline: 1.1099x; 1.1099x over previous
#include <cuda_runtime.h>

// GenLoss, fused single kernel, low-pressure arrival protocol.
// combined = mean_b( masked-mean_c( MAE(out,target)[b,c] ) ) - 0.01*mean(labels)/(epoch+1)
//
// 768 image blocks + 8 label blocks (776 total; single wave: 8 blocks/SM *
// 148 SMs = 1184 slots). Each non-finalizer block writes its partial, fences,
// and fire-and-forget RED-increments ONE counter (one-shot REDs are ~1cyc/op
// at L2 — cheap; R4's mistake was the returning-ATOMG + full-block wait, R8's
// was 256-thread flag polling that starved the finalizer's SM at ~80% of the
// LSU issue floor). The finalizer polls with a SINGLE thread at 1 poll/us,
// then folds all partials in fixed order (deterministic) and resets state.

#define PLANES      48
#define BPP         16
#define RBLOCKS     (PLANES * BPP)      // 768
#define LBLOCKS     8
#define TOTAL_BLK   (RBLOCKS + LBLOCKS) // 776
#define FIN_BLK     (TOTAL_BLK - 1)
#define THREADS     256
#define PLANE_ELEMS (512*512)
#define BLOCK_ELEMS (PLANE_ELEMS/BPP)          // 16384
#define VEC_ITERS   (BLOCK_ELEMS/(THREADS*4))  // 16

__device__ float g_psum[RBLOCKS];
__device__ int   g_pflag[RBLOCKS];
__device__ float g_lsum[LBLOCKS];
__device__ int   g_done;               // zero-init; reset by finalizer each run

__global__ void __launch_bounds__(THREADS, 8)
k_genloss(const float* __restrict__ out_img, const float* __restrict__ tgt_img,
          const float* __restrict__ labels, int n_labels,
          const int* __restrict__ epoch, float* __restrict__ out)
{
    const int tid = threadIdx.x;
    const int wid = tid >> 5;
    const int lid = tid & 31;
    const int bid = blockIdx.x;

    __shared__ float ss[THREADS / 32];
    __shared__ int   sf[THREADS / 32];

    if (bid < RBLOCKS) {
        // ---- image MAE partial over 1/16th of one plane ----
        const int plane = bid / BPP;
        const int sub   = bid % BPP;
        const long base = (long)plane * PLANE_ELEMS + (long)sub * BLOCK_ELEMS;

        const float4* __restrict__ o = (const float4*)(out_img + base);
        const float4* __restrict__ t = (const float4*)(tgt_img + base);

        float s = 0.0f;
        int   flag = 0;
        #pragma unroll
        for (int j = 0; j < VEC_ITERS; j++) {
            float4 a = o[tid + j * THREADS];
            float4 b = t[tid + j * THREADS];
            s += fabsf(a.x - b.x) + fabsf(a.y - b.y)
               + fabsf(a.z - b.z) + fabsf(a.w - b.w);
            flag |= (b.x != 0.0f) | (b.y != 0.0f) | (b.z != 0.0f) | (b.w != 0.0f);
        }
        #pragma unroll
        for (int off = 16; off; off >>= 1) {
            s    += __shfl_down_sync(0xffffffffu, s, off);
            flag |= __shfl_down_sync(0xffffffffu, flag, off);
        }
        if (lid == 0) { ss[wid] = s; sf[wid] = flag; }
        __syncthreads();
        if (tid == 0) {
            float bs = 0.0f; int bf = 0;
            #pragma unroll
            for (int w = 0; w < THREADS / 32; w++) { bs += ss[w]; bf |= sf[w]; }
            g_psum[bid]  = bs;
            g_pflag[bid] = bf;
            __threadfence();
            atomicAdd(&g_done, 1);    // fire-and-forget (RED), one-shot
        }
        return;
    }

    // ---- label partial sum (blocks 768..775) ----
    const int lb = bid - RBLOCKS;
    {
        float s = 0.0f;
        for (int i = lb * THREADS + tid; i < n_labels; i += LBLOCKS * THREADS)
            s += labels[i];
        #pragma unroll
        for (int off = 16; off; off >>= 1)
            s += __shfl_down_sync(0xffffffffu, s, off);
        if (lid == 0) ss[wid] = s;
        __syncthreads();
        if (tid == 0) {
            float bs = 0.0f;
            #pragma unroll
            for (int w = 0; w < THREADS / 32; w++) bs += ss[w];
            g_lsum[lb] = bs;
            if (bid != FIN_BLK) {
                __threadfence();
                atomicAdd(&g_done, 1);
            }
        }
    }
    if (bid != FIN_BLK) return;

    // ================= finalizer (block 775) =================
    // ONE thread polls the counter at ~1 poll/us: zero pressure on this SM's
    // LSU, so co-resident streaming blocks run at full speed. Grid is one
    // wave, so every other block is resident -> counter WILL reach 775.
    if (tid == 0) {
        volatile int* vd = &g_done;
        while (*vd != TOTAL_BLK - 1) __nanosleep(1000);
    }
    __syncthreads();
    __threadfence();   // acquire: order partial reads after counter observation

    __shared__ float sp[RBLOCKS];
    __shared__ int   sfl[RBLOCKS];
    __shared__ float plane_mae[PLANES];
    __shared__ int   plane_valid[PLANES];

    // Parallel vectorized fetch of partials (one L2 latency round-trip).
    const float4* ps4 = (const float4*)g_psum;
    const int4*   pf4 = (const int4*)g_pflag;
    if (tid < RBLOCKS / 4) {
        float4 v = ps4[tid];
        int4   f = pf4[tid];
        sp[tid * 4 + 0] = v.x;  sp[tid * 4 + 1] = v.y;
        sp[tid * 4 + 2] = v.z;  sp[tid * 4 + 3] = v.w;
        sfl[tid * 4 + 0] = f.x; sfl[tid * 4 + 1] = f.y;
        sfl[tid * 4 + 2] = f.z; sfl[tid * 4 + 3] = f.w;
    }
    __syncthreads();

    if (tid < PLANES) {
        float s = 0.0f; int f = 0;
        #pragma unroll
        for (int i = 0; i < BPP; i++) {
            s += sp[tid * BPP + i];
            f |= sfl[tid * BPP + i];
        }
        plane_mae[tid]   = s * (1.0f / (float)PLANE_ELEMS);
        plane_valid[tid] = f;
    }
    __syncthreads();

    if (tid == 0) {
        float lsum = 0.0f;
        #pragma unroll
        for (int i = 0; i < LBLOCKS; i++) lsum += g_lsum[i];
        const float lmean = lsum / (float)n_labels;

        float img = 0.0f;
        #pragma unroll
        for (int b = 0; b < 16; b++) {
            float tot = 0.0f, cnt = 0.0f;
            #pragma unroll
            for (int c = 0; c < 3; c++) {
                const int p = b * 3 + c;
                if (plane_valid[p]) { tot += plane_mae[p]; cnt += 1.0f; }
            }
            img += (cnt > 0.0f) ? (tot / cnt) : 0.0f;
        }
        img *= (1.0f / 16.0f);

        out[0] = img + 0.01f * (-lmean) / (float)(epoch[0] + 1);
        g_done = 0;    // reset for next graph replay (all adds already observed)
    }
}

extern "C" void kernel_launch(void* const* d_in, const int* in_sizes, int n_in,
                              void* d_out, int out_size)
{
    const float* labels  = (const float*)d_in[0];
    const float* out_img = (const float*)d_in[1];
    const float* tgt_img = (const float*)d_in[2];
    const int*   epoch   = (const int*)d_in[3];
    float*       out     = (float*)d_out;

    k_genloss<<<TOTAL_BLK, THREADS>>>(out_img, tgt_img, labels, in_sizes[0], epoch, out);
}